// round 3
// baseline (speedup 1.0000x reference)
#include <cuda_runtime.h>
#include <cuda_bf16.h>

#define C 4096
#define COLS_PER_BLOCK 8
#define NBLOCKS (C / COLS_PER_BLOCK)   // 512 blocks
#define THREADS 256

// Scratch (allocation-free rule: __device__ globals). float4-aligned.
__device__ float4 g_x3v[3 * C / 4];    // xk | xv | xr

// ---------------------------------------------------------------------------
// K1: token-shift mix + new_state copy + zero out[0:C] (atomic accum target)
// ---------------------------------------------------------------------------
__global__ void mix_kernel(const float* __restrict__ x,
                           const float* __restrict__ state,
                           const float* __restrict__ tmk,
                           const float* __restrict__ tmv,
                           const float* __restrict__ tmr,
                           float* __restrict__ d_out) {
    int i = blockIdx.x * blockDim.x + threadIdx.x;
    if (i >= C) return;
    float* g_x3 = reinterpret_cast<float*>(g_x3v);
    float xi = x[i];
    float si = state[i];
    float mk = tmk[i], mv = tmv[i], mr = tmr[i];
    g_x3[i]         = xi * mk + si * (1.0f - mk);
    g_x3[C + i]     = xi * mv + si * (1.0f - mv);
    g_x3[2 * C + i] = xi * mr + si * (1.0f - mr);
    d_out[i]     = 0.0f;   // out accumulator
    d_out[C + i] = xi;     // new_state
}

// One warp computes dot(W_row[0:C], xvec[0:C]). W streamed (__ldcs),
// x via read-only cache (L1-resident, shared by all warps in the SM).
__device__ __forceinline__ float row_dot(const float* __restrict__ Wrow,
                                         const float4* __restrict__ xv,
                                         int lane) {
    const float4* Wr = reinterpret_cast<const float4*>(Wrow);
    float4 a0 = make_float4(0.f, 0.f, 0.f, 0.f);
    float4 a1 = make_float4(0.f, 0.f, 0.f, 0.f);
#pragma unroll
    for (int j = 0; j < 32; j += 2) {
        float4 w0 = __ldcs(&Wr[lane + (j + 0) * 32]);
        float4 w1 = __ldcs(&Wr[lane + (j + 1) * 32]);
        float4 x0 = __ldg(&xv[lane + (j + 0) * 32]);
        float4 x1 = __ldg(&xv[lane + (j + 1) * 32]);
        a0.x = fmaf(w0.x, x0.x, a0.x); a0.y = fmaf(w0.y, x0.y, a0.y);
        a0.z = fmaf(w0.z, x0.z, a0.z); a0.w = fmaf(w0.w, x0.w, a0.w);
        a1.x = fmaf(w1.x, x1.x, a1.x); a1.y = fmaf(w1.y, x1.y, a1.y);
        a1.z = fmaf(w1.z, x1.z, a1.z); a1.w = fmaf(w1.w, x1.w, a1.w);
    }
    float s = ((a0.x + a0.y) + (a0.z + a0.w))
            + ((a1.x + a1.y) + (a1.z + a1.w));
#pragma unroll
    for (int o = 16; o > 0; o >>= 1)
        s += __shfl_xor_sync(0xFFFFFFFFu, s, o);
    return s;
}

// ---------------------------------------------------------------------------
// K2 (fused): block b owns columns j0..j0+7.
//   Phase A: warp w computes kk/vv/rr for column j0+w (3 row-dots).
//   Phase B: threads 0..7 do the elementwise wkv for the 8 columns,
//            write new_state_a/b/p, produce y[c] = r*wkv.
//   Phase C: stream ow[:, j0:j0+8] and atomically accumulate partial out.
// No inter-block dependency -> all 256 MB stream back-to-back chip-wide.
// ---------------------------------------------------------------------------
__global__ __launch_bounds__(THREADS)
void fused_kernel(const float* __restrict__ kw,
                  const float* __restrict__ vw,
                  const float* __restrict__ rw,
                  const float* __restrict__ ow,
                  const float* __restrict__ state_a,
                  const float* __restrict__ state_b,
                  const float* __restrict__ state_p,
                  const float* __restrict__ time_first,
                  const float* __restrict__ time_decay,
                  float* __restrict__ d_out) {
    __shared__ float s_kvr[3 * COLS_PER_BLOCK];
    __shared__ __align__(16) float s_y[COLS_PER_BLOCK];

    int tid  = threadIdx.x;
    int w    = tid >> 5;
    int lane = tid & 31;
    int j0   = blockIdx.x * COLS_PER_BLOCK;
    int j    = j0 + w;                 // column owned by this warp

    const float4* xk = g_x3v;
    const float4* xv = g_x3v + C / 4;
    const float4* xr = g_x3v + 2 * (C / 4);

    // ---- Phase A: 3 row-dots per warp
    float dk = row_dot(kw + (size_t)j * C, xk, lane);
    float dv = row_dot(vw + (size_t)j * C, xv, lane);
    float dr = row_dot(rw + (size_t)j * C, xr, lane);
    if (lane == 0) {
        s_kvr[w]                      = dk;
        s_kvr[COLS_PER_BLOCK + w]     = dv;
        s_kvr[2 * COLS_PER_BLOCK + w] = dr;
    }
    __syncthreads();

    // ---- Phase B: elementwise wkv for the block's 8 columns
    if (tid < COLS_PER_BLOCK) {
        int jj = j0 + tid;
        float kk = s_kvr[tid];
        float vv = s_kvr[COLS_PER_BLOCK + tid];
        float rr = s_kvr[2 * COLS_PER_BLOCK + tid];
        float aa = state_a[jj];
        float bb = state_b[jj];
        float pp = state_p[jj];
        float tf = time_first[jj];
        float td = time_decay[jj];

        float r = 1.0f / (1.0f + expf(-rr));

        float ww = tf + kk;
        float p  = fmaxf(pp, ww);
        float e1 = expf(pp - p);
        float e2 = expf(ww - p);
        float a  = e1 * aa + e2 * vv;
        float b  = e1 * bb + e2;

        float ww2 = pp + td;
        float p2  = fmaxf(ww2, kk);
        float f1  = expf(ww2 - p2);
        float f2  = expf(kk - p2);

        d_out[2 * C + jj] = f1 * aa + f2 * vv;  // new_state_a
        d_out[3 * C + jj] = f1 * bb + f2;       // new_state_b
        d_out[4 * C + jj] = p2;                 // new_state_p

        s_y[tid] = r * (a / b);
    }
    __syncthreads();

    // ---- Phase C: out += ow[:, j0:j0+8] @ y
    // Lane layout: lane covers row (base + lane>>1), cols (lane&1)*4..+3.
    // One LDG.128/lane = 16 rows x 32B, fully sector-coalesced.
    float4 yv = reinterpret_cast<const float4*>(s_y)[lane & 1];
    int c4 = (lane & 1) * 4;
    int row_base = w * (C / COLS_PER_BLOCK);   // 512 rows per warp
#pragma unroll 4
    for (int it = 0; it < (C / COLS_PER_BLOCK) / 16; it++) {
        int row = row_base + it * 16 + (lane >> 1);
        const float4* Or = reinterpret_cast<const float4*>(ow + (size_t)row * C + j0 + c4);
        float4 wv = __ldcs(Or);
        float s = fmaf(wv.x, yv.x,
                  fmaf(wv.y, yv.y,
                  fmaf(wv.z, yv.z, wv.w * yv.w)));
        s += __shfl_xor_sync(0xFFFFFFFFu, s, 1);
        if ((lane & 1) == 0)
            atomicAdd(&d_out[row], s);
    }
}

// ---------------------------------------------------------------------------
// Launch. Input order (metadata): x, state, state_a, state_b, state_p,
// time_mix_k, time_mix_v, time_mix_r, time_first, time_decay, kw, vw, rw, ow.
// Output layout: [out | new_state | new_state_a | new_state_b | new_state_p]
// ---------------------------------------------------------------------------
extern "C" void kernel_launch(void* const* d_in, const int* in_sizes, int n_in,
                              void* d_out, int out_size) {
    const float* x   = (const float*)d_in[0];
    const float* st  = (const float*)d_in[1];
    const float* sa  = (const float*)d_in[2];
    const float* sb  = (const float*)d_in[3];
    const float* sp  = (const float*)d_in[4];
    const float* tmk = (const float*)d_in[5];
    const float* tmv = (const float*)d_in[6];
    const float* tmr = (const float*)d_in[7];
    const float* tf  = (const float*)d_in[8];
    const float* td  = (const float*)d_in[9];
    const float* kw  = (const float*)d_in[10];
    const float* vw  = (const float*)d_in[11];
    const float* rw  = (const float*)d_in[12];
    const float* ow  = (const float*)d_in[13];
    float* out = (float*)d_out;

    mix_kernel<<<C / 256, 256>>>(x, st, tmk, tmv, tmr, out);
    fused_kernel<<<NBLOCKS, THREADS>>>(kw, vw, rw, ow, sa, sb, sp, tf, td, out);
}

// round 4
// speedup vs baseline: 1.1986x; 1.1986x over previous
#include <cuda_runtime.h>
#include <cuda_bf16.h>

#define C 4096
#define ROWS_PER_BLOCK 8      // 8 warps, one row each
#define MV_THREADS 256

// Scratch (allocation-free rule: __device__ globals)
__device__ float g_x3[3 * C];    // xk | xv | xr
__device__ float g_kvr[3 * C];   // kk | vv | rr  (atomic accumulation)
__device__ float g_rwkv[C];      // r * wkv

// ---------------------------------------------------------------------------
// K1: token-shift mix + new_state copy + zero accumulators
// ---------------------------------------------------------------------------
__global__ void mix_kernel(const float* __restrict__ x,
                           const float* __restrict__ state,
                           const float* __restrict__ tmk,
                           const float* __restrict__ tmv,
                           const float* __restrict__ tmr,
                           float* __restrict__ d_out) {
    int i = blockIdx.x * blockDim.x + threadIdx.x;
    if (i >= C) return;
    float xi = x[i];
    float si = state[i];
    float mk = tmk[i], mv = tmv[i], mr = tmr[i];
    g_x3[i]         = xi * mk + si * (1.0f - mk);
    g_x3[C + i]     = xi * mv + si * (1.0f - mv);
    g_x3[2 * C + i] = xi * mr + si * (1.0f - mr);
    g_kvr[i]         = 0.0f;
    g_kvr[C + i]     = 0.0f;
    g_kvr[2 * C + i] = 0.0f;
    d_out[i]     = 0.0f;   // out accumulator (matvec_ow atomics)
    d_out[C + i] = xi;     // new_state
}

// Partial dot over CHUNK float4s per lane. W streamed once (__ldcs),
// x via read-only path (L1-resident across the block's warps).
template <int CHUNK4>   // float4 elements per lane
__device__ __forceinline__ float partial_dot(const float4* __restrict__ Wr,
                                             const float4* __restrict__ xv,
                                             int lane) {
    float4 a0 = make_float4(0.f, 0.f, 0.f, 0.f);
    float4 a1 = make_float4(0.f, 0.f, 0.f, 0.f);
#pragma unroll
    for (int j = 0; j < CHUNK4; j += 2) {
        float4 w0 = __ldcs(&Wr[lane + (j + 0) * 32]);
        float4 w1 = __ldcs(&Wr[lane + (j + 1) * 32]);
        float4 x0 = __ldg(&xv[lane + (j + 0) * 32]);
        float4 x1 = __ldg(&xv[lane + (j + 1) * 32]);
        a0.x = fmaf(w0.x, x0.x, a0.x); a0.y = fmaf(w0.y, x0.y, a0.y);
        a0.z = fmaf(w0.z, x0.z, a0.z); a0.w = fmaf(w0.w, x0.w, a0.w);
        a1.x = fmaf(w1.x, x1.x, a1.x); a1.y = fmaf(w1.y, x1.y, a1.y);
        a1.z = fmaf(w1.z, x1.z, a1.z); a1.w = fmaf(w1.w, x1.w, a1.w);
    }
    float s = ((a0.x + a0.y) + (a0.z + a0.w))
            + ((a1.x + a1.y) + (a1.z + a1.w));
#pragma unroll
    for (int o = 16; o > 0; o >>= 1)
        s += __shfl_xor_sync(0xFFFFFFFFu, s, o);
    return s;
}

// ---------------------------------------------------------------------------
// K2: kw@xk, vw@xv, rw@xr with K split in 2 chunks of 2048.
//     grid = (512, 2, 3) = 3072 blocks. Partials atomicAdd into g_kvr.
// ---------------------------------------------------------------------------
#define K_SPLIT3 2
#define CHUNK3 (C / K_SPLIT3)          // 2048 floats
__global__ __launch_bounds__(MV_THREADS)
void matvec3_kernel(const float* __restrict__ kw,
                    const float* __restrict__ vw,
                    const float* __restrict__ rw) {
    int mat   = blockIdx.z;
    int kc    = blockIdx.y;
    const float* W = (mat == 0) ? kw : (mat == 1) ? vw : rw;

    int tid  = threadIdx.x;
    int warp = tid >> 5;
    int lane = tid & 31;
    int row  = blockIdx.x * ROWS_PER_BLOCK + warp;
    int col0 = kc * CHUNK3;

    const float4* Wr = reinterpret_cast<const float4*>(W + (size_t)row * C + col0);
    const float4* xv = reinterpret_cast<const float4*>(g_x3 + mat * C + col0);

    float s = partial_dot<CHUNK3 / 128>(Wr, xv, lane);   // 16 float4 per lane
    if (lane == 0) atomicAdd(&g_kvr[mat * C + row], s);
}

// ---------------------------------------------------------------------------
// K3: elementwise WKV + state update. Writes new_state_a/b/p, stores r*wkv.
// ---------------------------------------------------------------------------
__global__ void wkv_kernel(const float* __restrict__ state_a,
                           const float* __restrict__ state_b,
                           const float* __restrict__ state_p,
                           const float* __restrict__ time_first,
                           const float* __restrict__ time_decay,
                           float* __restrict__ d_out) {
    int i = blockIdx.x * blockDim.x + threadIdx.x;
    if (i >= C) return;

    float kk = g_kvr[i];
    float vv = g_kvr[C + i];
    float rr = g_kvr[2 * C + i];
    float aa = state_a[i];
    float bb = state_b[i];
    float pp = state_p[i];
    float tf = time_first[i];
    float td = time_decay[i];

    float r = 1.0f / (1.0f + expf(-rr));

    float ww = tf + kk;
    float p  = fmaxf(pp, ww);
    float e1 = expf(pp - p);
    float e2 = expf(ww - p);
    float a  = e1 * aa + e2 * vv;
    float b  = e1 * bb + e2;

    float ww2 = pp + td;
    float p2  = fmaxf(ww2, kk);
    float f1  = expf(ww2 - p2);
    float f2  = expf(kk - p2);

    d_out[2 * C + i] = f1 * aa + f2 * vv;  // new_state_a
    d_out[3 * C + i] = f1 * bb + f2;       // new_state_b
    d_out[4 * C + i] = p2;                 // new_state_p

    g_rwkv[i] = r * (a / b);
}

// ---------------------------------------------------------------------------
// K4: out += ow @ (r*wkv), K split in 4 chunks of 1024.
//     grid = (512, 4) = 2048 blocks. Partials atomicAdd into d_out[0:C].
// ---------------------------------------------------------------------------
#define K_SPLIT_OW 4
#define CHUNK_OW (C / K_SPLIT_OW)      // 1024 floats
__global__ __launch_bounds__(MV_THREADS)
void matvec_ow_kernel(const float* __restrict__ ow,
                      float* __restrict__ out /* d_out */) {
    int kc   = blockIdx.y;
    int tid  = threadIdx.x;
    int warp = tid >> 5;
    int lane = tid & 31;
    int row  = blockIdx.x * ROWS_PER_BLOCK + warp;
    int col0 = kc * CHUNK_OW;

    const float4* Wr = reinterpret_cast<const float4*>(ow + (size_t)row * C + col0);
    const float4* xv = reinterpret_cast<const float4*>(g_rwkv + col0);

    float s = partial_dot<CHUNK_OW / 128>(Wr, xv, lane);  // 8 float4 per lane
    if (lane == 0) atomicAdd(&out[row], s);
}

// ---------------------------------------------------------------------------
// Launch. Input order (metadata): x, state, state_a, state_b, state_p,
// time_mix_k, time_mix_v, time_mix_r, time_first, time_decay, kw, vw, rw, ow.
// Output layout: [out | new_state | new_state_a | new_state_b | new_state_p]
// ---------------------------------------------------------------------------
extern "C" void kernel_launch(void* const* d_in, const int* in_sizes, int n_in,
                              void* d_out, int out_size) {
    const float* x   = (const float*)d_in[0];
    const float* st  = (const float*)d_in[1];
    const float* sa  = (const float*)d_in[2];
    const float* sb  = (const float*)d_in[3];
    const float* sp  = (const float*)d_in[4];
    const float* tmk = (const float*)d_in[5];
    const float* tmv = (const float*)d_in[6];
    const float* tmr = (const float*)d_in[7];
    const float* tf  = (const float*)d_in[8];
    const float* td  = (const float*)d_in[9];
    const float* kw  = (const float*)d_in[10];
    const float* vw  = (const float*)d_in[11];
    const float* rw  = (const float*)d_in[12];
    const float* ow  = (const float*)d_in[13];
    float* out = (float*)d_out;

    mix_kernel<<<C / 256, 256>>>(x, st, tmk, tmv, tmr, out);

    dim3 g2(C / ROWS_PER_BLOCK, K_SPLIT3, 3);
    matvec3_kernel<<<g2, MV_THREADS>>>(kw, vw, rw);

    wkv_kernel<<<C / 256, 256>>>(sa, sb, sp, tf, td, out);

    dim3 g4(C / ROWS_PER_BLOCK, K_SPLIT_OW);
    matvec_ow_kernel<<<g4, MV_THREADS>>>(ow, out);
}